// round 8
// baseline (speedup 1.0000x reference)
#include <cuda_runtime.h>
#include <cuda_fp16.h>
#include <cstdint>

#define IN_DIM 128
#define OUT_DIM 64
#define MAXN 50000
#define MAXE 1600000
#define SLOPE 0.1f
#define EPS 1e-12f
#define SCAN_BLK 1024
#define MAX_SCAN_BLOCKS 64
#define TILE_ROWS 128
// dynamic smem: xs[128][128] fp32 + wT[128][64] fp32
#define SMEM_XS_FLOATS (TILE_ROWS * IN_DIM)
#define SMEM_WT_FLOATS (IN_DIM * OUT_DIM)
#define SMEM_BYTES ((SMEM_XS_FLOATS + SMEM_WT_FLOATS) * 4)

// Scratch (static device globals — allocation is forbidden). Zero-init at load.
__device__ __align__(256) __half g_newh[MAXN * OUT_DIM]; // transformed features, fp16
__device__ float  g_ssrc[MAXN];          // new[n] . a_src
__device__ float  g_sdst[MAXN];          // new[n] . a_dst
__device__ int    g_cnt[MAXN];           // out-degree histogram (zeroed by k_aggregate)
__device__ int    g_base[MAXN];          // CSR offsets (mutated by k_place into end[])
__device__ __align__(16) float2 g_edge[MAXE];  // src-sorted {ev, dst_bits}
__device__ int    g_bsum[MAX_SCAN_BLOCKS];
__device__ int    g_flag[MAX_SCAN_BLOCKS];

// ---------------------------------------------------------------------------
// Kernel 1 (fused): blocks [0, nbT): register-tiled transform.
//   Block tile = 128 nodes x 64 outs, K=128. Thread = 8x4 micro-tile.
//   x staged coalesced -> smem (STS.128, conflict-free); W transposed in smem.
//   12 LDS.128 per 128 FFMA. Scores reduced via 16-lane shfl_xor.
// Blocks [nbT,...): histogram of src (no smem use).
// ---------------------------------------------------------------------------
__global__ __launch_bounds__(256) void k_fused(
    const float* __restrict__ x, const float* __restrict__ W,
    const float* __restrict__ b, const float* __restrict__ a,
    const int* __restrict__ eidx, int nN, int nE, int nbT)
{
    if ((int)blockIdx.x >= nbT) {
        // ---- histogram part ----
        int tidg   = (blockIdx.x - nbT) * blockDim.x + threadIdx.x;
        int stride = (gridDim.x - nbT) * blockDim.x;
        for (int e = tidg; e < nE; e += stride) {
            int s = eidx[e];
            s = min(max(s, 0), nN - 1);
            atomicAdd(&g_cnt[s], 1);
        }
        return;
    }

    // ---- transform part ----
    extern __shared__ float smem[];
    float* xs = smem;                       // [row][k], row stride 128
    float* wT = smem + SMEM_XS_FLOATS;      // [k][d], row stride 64
    __shared__ float sb[OUT_DIM], sas[OUT_DIM], sad[OUT_DIM];

    int tid = threadIdx.x;
    if (blockIdx.x == 0 && tid < MAX_SCAN_BLOCKS) g_flag[tid] = 0;

    // stage W transposed: wT[k][d] = W[d][k]
    for (int i = tid; i < OUT_DIM * IN_DIM; i += 256) {
        int k = i >> 6;          // 0..127
        int d = i & 63;          // 0..63
        wT[k * OUT_DIM + d] = W[d * IN_DIM + k];
    }
    if (tid < OUT_DIM) {
        sb[tid]  = b[tid];
        sas[tid] = a[tid];
        sad[tid] = a[OUT_DIM + tid];
    }

    int rowBase = blockIdx.x * TILE_ROWS;
    // stage x: warp covers one row's 32 float4 (coalesced); STS.128 conflict-free
    for (int i = tid; i < TILE_ROWS * (IN_DIM / 4); i += 256) {
        int r  = i >> 5;         // 0..127
        int kk = i & 31;         // 0..31
        int gr = rowBase + r;
        float4 xv = (gr < nN) ? ((const float4*)x)[(size_t)gr * (IN_DIM / 4) + kk]
                              : make_float4(0.f, 0.f, 0.f, 0.f);
        *(float4*)&xs[r * IN_DIM + kk * 4] = xv;
    }
    __syncthreads();

    int tx = tid & 15;           // output-col group: d0 = tx*4
    int ty = tid >> 4;           // row group: r0 = ty*8
    int r0 = ty * 8, d0 = tx * 4;

    float acc[8][4];
#pragma unroll
    for (int u = 0; u < 8; u++)
#pragma unroll
        for (int j = 0; j < 4; j++) acc[u][j] = 0.f;

    for (int k4 = 0; k4 < IN_DIM / 4; k4++) {
        float4 xr[8];
#pragma unroll
        for (int u = 0; u < 8; u++)
            xr[u] = *(const float4*)&xs[(r0 + u) * IN_DIM + k4 * 4];   // broadcast
#pragma unroll
        for (int q = 0; q < 4; q++) {
            float4 wv = *(const float4*)&wT[(k4 * 4 + q) * OUT_DIM + d0];
#pragma unroll
            for (int u = 0; u < 8; u++) {
                float xv = (q == 0) ? xr[u].x : (q == 1) ? xr[u].y
                         : (q == 2) ? xr[u].z : xr[u].w;
                acc[u][0] += xv * wv.x;
                acc[u][1] += xv * wv.y;
                acc[u][2] += xv * wv.z;
                acc[u][3] += xv * wv.w;
            }
        }
    }

    // epilogue: bias, fp16 store, score partials + 16-lane reduction
#pragma unroll
    for (int u = 0; u < 8; u++) {
        int gr = rowBase + r0 + u;
        float v0 = acc[u][0] + sb[d0 + 0];
        float v1 = acc[u][1] + sb[d0 + 1];
        float v2 = acc[u][2] + sb[d0 + 2];
        float v3 = acc[u][3] + sb[d0 + 3];
        if (gr < nN) {
            __half2 h0 = __float22half2_rn(make_float2(v0, v1));
            __half2 h1 = __float22half2_rn(make_float2(v2, v3));
            uint2 hv;
            hv.x = *(unsigned int*)&h0;
            hv.y = *(unsigned int*)&h1;
            *(uint2*)&g_newh[(size_t)gr * OUT_DIM + d0] = hv;   // coalesced
        }
        float ssp = v0*sas[d0+0] + v1*sas[d0+1] + v2*sas[d0+2] + v3*sas[d0+3];
        float sdp = v0*sad[d0+0] + v1*sad[d0+1] + v2*sad[d0+2] + v3*sad[d0+3];
#pragma unroll
        for (int off = 8; off > 0; off >>= 1) {
            ssp += __shfl_xor_sync(0xFFFFFFFF, ssp, off, 16);
            sdp += __shfl_xor_sync(0xFFFFFFFF, sdp, off, 16);
        }
        if (tx == 0 && gr < nN) {
            g_ssrc[gr] = ssp;
            g_sdst[gr] = sdp;
        }
    }
}

// ---------------------------------------------------------------------------
// Kernel 2: exclusive scan of g_cnt -> g_base, decoupled lookback.
// ---------------------------------------------------------------------------
__global__ __launch_bounds__(SCAN_BLK) void k_scan(int nN)
{
    __shared__ int swarp[32];
    __shared__ int s_total;
    __shared__ int s_boff;
    int tid  = threadIdx.x;
    int lane = tid & 31;
    int wid  = tid >> 5;
    int bid  = blockIdx.x;
    int i    = bid * SCAN_BLK + tid;

    int v = (i < nN) ? g_cnt[i] : 0;

    int inc = v;
#pragma unroll
    for (int off = 1; off < 32; off <<= 1) {
        int t = __shfl_up_sync(0xFFFFFFFF, inc, off);
        if (lane >= off) inc += t;
    }
    if (lane == 31) swarp[wid] = inc;
    __syncthreads();
    if (wid == 0) {
        int wv = swarp[lane];
        int winc = wv;
#pragma unroll
        for (int off = 1; off < 32; off <<= 1) {
            int t = __shfl_up_sync(0xFFFFFFFF, winc, off);
            if (lane >= off) winc += t;
        }
        swarp[lane] = winc - wv;
    }
    __syncthreads();
    int incl = swarp[wid] + inc;
    if (tid == SCAN_BLK - 1) s_total = incl;
    __syncthreads();

    if (tid == 0) {
        g_bsum[bid] = s_total;
        __threadfence();
        *(volatile int*)&g_flag[bid] = 1;
    }

    if (wid == 0) {
        int off = 0;
        for (int base = 0; base < bid; base += 32) {
            int j = base + lane;
            int vj = 0;
            if (j < bid) {
                while (*(volatile int*)&g_flag[j] == 0) {}
                __threadfence();
                vj = *(volatile int*)&g_bsum[j];
            }
#pragma unroll
            for (int o = 16; o > 0; o >>= 1)
                vj += __shfl_down_sync(0xFFFFFFFF, vj, o);
            off += __shfl_sync(0xFFFFFFFF, vj, 0);
        }
        if (lane == 0) s_boff = off;
    }
    __syncthreads();

    if (i < nN) g_base[i] = s_boff + incl - v;
}

// ---------------------------------------------------------------------------
// Kernel 3: place, 2 edges/thread (int2 loads, 4 independent gathers in
// flight — latency-bound fix). Cursor atomic leaves g_base[n] == end[n].
// ---------------------------------------------------------------------------
__global__ __launch_bounds__(256) void k_place(
    const int* __restrict__ eidx, int nE, int nN)
{
    int i = blockIdx.x * blockDim.x + threadIdx.x;   // pair index
    int e0 = i * 2;
    if (e0 >= nE) return;

    if (e0 + 1 < nE) {
        int2 sp = ((const int2*)eidx)[i];
        int2 dp = ((const int2*)(eidx + nE))[i];
        int s0 = min(max(sp.x, 0), nN - 1), s1 = min(max(sp.y, 0), nN - 1);
        int d0 = min(max(dp.x, 0), nN - 1), d1 = min(max(dp.y, 0), nN - 1);
        float a0 = g_ssrc[s0], a1 = g_ssrc[s1];
        float b0 = g_sdst[d0], b1 = g_sdst[d1];
        float sc0 = a0 + b0, sc1 = a1 + b1;
        sc0 = sc0 > 0.f ? sc0 : SLOPE * sc0;
        sc1 = sc1 > 0.f ? sc1 : SLOPE * sc1;
        float ev0 = __expf(sc0), ev1 = __expf(sc1);
        int p0 = atomicAdd(&g_base[s0], 1);
        int p1 = atomicAdd(&g_base[s1], 1);
        g_edge[p0] = make_float2(ev0, __int_as_float(d0));
        g_edge[p1] = make_float2(ev1, __int_as_float(d1));
    } else {
        int s = min(max(eidx[e0], 0), nN - 1);
        int d = min(max(eidx[(size_t)nE + e0], 0), nN - 1);
        float sc = g_ssrc[s] + g_sdst[d];
        sc = sc > 0.f ? sc : SLOPE * sc;
        float ev = __expf(sc);
        int pos = atomicAdd(&g_base[s], 1);
        g_edge[pos] = make_float2(ev, __int_as_float(d));
    }
}

// ---------------------------------------------------------------------------
// Kernel 4: gather-aggregate + normalize. 8 lanes/node, lane c owns 16B of
// the fp16 row. Unrolled x4 for MLP. Re-zeroes g_cnt for graph replay.
// ---------------------------------------------------------------------------
__global__ __launch_bounds__(256) void k_aggregate(
    float* __restrict__ out, int nN)
{
    int n = blockIdx.x * 32 + (threadIdx.x >> 3);
    int c = threadIdx.x & 7;
    if (n >= nN) return;

    int beg = (n == 0) ? 0 : g_base[n - 1];
    int end = g_base[n];

    float acc[8];
#pragma unroll
    for (int j = 0; j < 8; j++) acc[j] = 0.f;
    float rs = 0.f;

    int i = beg;
    for (; i + 4 <= end; i += 4) {
        float2 p0 = g_edge[i];
        float2 p1 = g_edge[i + 1];
        float2 p2 = g_edge[i + 2];
        float2 p3 = g_edge[i + 3];
        uint4 h0 = *(const uint4*)(g_newh + ((size_t)__float_as_int(p0.y) << 6) + c * 8);
        uint4 h1 = *(const uint4*)(g_newh + ((size_t)__float_as_int(p1.y) << 6) + c * 8);
        uint4 h2 = *(const uint4*)(g_newh + ((size_t)__float_as_int(p2.y) << 6) + c * 8);
        uint4 h3 = *(const uint4*)(g_newh + ((size_t)__float_as_int(p3.y) << 6) + c * 8);
#pragma unroll
        for (int q = 0; q < 4; q++) {
            float ev = (q == 0) ? p0.x : (q == 1) ? p1.x : (q == 2) ? p2.x : p3.x;
            uint4 hv = (q == 0) ? h0 : (q == 1) ? h1 : (q == 2) ? h2 : h3;
            float2 f0 = __half22float2(*(__half2*)&hv.x);
            float2 f1 = __half22float2(*(__half2*)&hv.y);
            float2 f2 = __half22float2(*(__half2*)&hv.z);
            float2 f3 = __half22float2(*(__half2*)&hv.w);
            acc[0] += ev * f0.x;  acc[1] += ev * f0.y;
            acc[2] += ev * f1.x;  acc[3] += ev * f1.y;
            acc[4] += ev * f2.x;  acc[5] += ev * f2.y;
            acc[6] += ev * f3.x;  acc[7] += ev * f3.y;
            rs += ev;
        }
    }
    for (; i < end; i++) {
        float2 p = g_edge[i];
        uint4 hv = *(const uint4*)(g_newh + ((size_t)__float_as_int(p.y) << 6) + c * 8);
        float ev = p.x;
        float2 f0 = __half22float2(*(__half2*)&hv.x);
        float2 f1 = __half22float2(*(__half2*)&hv.y);
        float2 f2 = __half22float2(*(__half2*)&hv.z);
        float2 f3 = __half22float2(*(__half2*)&hv.w);
        acc[0] += ev * f0.x;  acc[1] += ev * f0.y;
        acc[2] += ev * f1.x;  acc[3] += ev * f1.y;
        acc[4] += ev * f2.x;  acc[5] += ev * f2.y;
        acc[6] += ev * f3.x;  acc[7] += ev * f3.y;
        rs += ev;
    }

    float inv = 1.f / (rs + EPS);
    float* op = out + ((size_t)n << 6) + c * 8;
    *(float4*)op       = make_float4(acc[0]*inv, acc[1]*inv, acc[2]*inv, acc[3]*inv);
    *(float4*)(op + 4) = make_float4(acc[4]*inv, acc[5]*inv, acc[6]*inv, acc[7]*inv);

    if (c == 0) g_cnt[n] = 0;   // clean for next launch (graph replay)
}

// ---------------------------------------------------------------------------
extern "C" void kernel_launch(void* const* d_in, const int* in_sizes, int n_in,
                              void* d_out, int out_size)
{
    const float* x    = (const float*)d_in[0];
    const int*   eidx = (const int*)d_in[1];    // int32 (JAX x64 disabled)
    const float* W    = (const float*)d_in[2];
    const float* b    = (const float*)d_in[3];
    const float* a    = (const float*)d_in[4];
    float* out = (float*)d_out;

    int nN = in_sizes[0] / IN_DIM;   // 50000
    int nE = in_sizes[1] / 2;        // 1600000

    cudaFuncSetAttribute(k_fused, cudaFuncAttributeMaxDynamicSharedMemorySize,
                         SMEM_BYTES);

    int nbT = (nN + TILE_ROWS - 1) / TILE_ROWS;   // 391
    int nbH = 1024;
    k_fused<<<nbT + nbH, 256, SMEM_BYTES>>>(x, W, b, a, eidx, nN, nE, nbT);

    int nbS = (nN + SCAN_BLK - 1) / SCAN_BLK;     // 49
    k_scan<<<nbS, SCAN_BLK>>>(nN);

    int pairs = (nE + 1) / 2;
    k_place<<<(pairs + 255) / 256, 256>>>(eidx, nE, nN);

    k_aggregate<<<(nN + 31) / 32, 256>>>(out, nN);
}

// round 9
// speedup vs baseline: 1.0176x; 1.0176x over previous
#include <cuda_runtime.h>
#include <cuda_fp16.h>
#include <cstdint>

#define IN_DIM 128
#define OUT_DIM 64
#define MAXN 50000
#define MAXE 1600000
#define SLOPE 0.1f
#define EPS 1e-12f
#define SCAN_BLK 1024
#define MAX_SCAN_BLOCKS 64

// Scratch (static device globals — allocation is forbidden). Zero-init at load.
__device__ __align__(256) __half g_newh[MAXN * OUT_DIM]; // transformed features, fp16
__device__ float  g_ssrc[MAXN];          // new[n] . a_src
__device__ float  g_sdst[MAXN];          // new[n] . a_dst
__device__ int    g_cnt[MAXN];           // out-degree histogram (zeroed by k_aggregate)
__device__ int    g_base[MAXN];          // CSR offsets (mutated by k_place into end[])
__device__ __align__(16) float2 g_edge[MAXE];  // src-sorted {ev, dst_bits}
__device__ int    g_bsum[MAX_SCAN_BLOCKS];
__device__ int    g_flag[MAX_SCAN_BLOCKS];

// ---------------------------------------------------------------------------
// Kernel 1 (fused): blocks [0, nbT): transform new = x@W^T+b -> fp16, scores
//   (scalar FFMA, W broadcast from smem — proven R4 form).
//   Blocks [nbT, ...): histogram of src. Block 0 zeroes scan flags.
// ---------------------------------------------------------------------------
__global__ __launch_bounds__(256) void k_fused(
    const float* __restrict__ x, const float* __restrict__ W,
    const float* __restrict__ b, const float* __restrict__ a,
    const int* __restrict__ eidx, int nN, int nE, int nbT)
{
    if ((int)blockIdx.x >= nbT) {
        // ---- histogram part ----
        int tidg   = (blockIdx.x - nbT) * blockDim.x + threadIdx.x;
        int stride = (gridDim.x - nbT) * blockDim.x;
        for (int e = tidg; e < nE; e += stride) {
            int s = eidx[e];
            s = min(max(s, 0), nN - 1);
            atomicAdd(&g_cnt[s], 1);
        }
        return;
    }

    // ---- transform part ----
    if (blockIdx.x == 0 && threadIdx.x < MAX_SCAN_BLOCKS) g_flag[threadIdx.x] = 0;

    __shared__ __align__(16) float sW[OUT_DIM * IN_DIM];
    __shared__ float sb[OUT_DIM], sas[OUT_DIM], sad[OUT_DIM];
    for (int i = threadIdx.x; i < OUT_DIM * IN_DIM; i += blockDim.x) sW[i] = W[i];
    if (threadIdx.x < OUT_DIM) {
        sb[threadIdx.x]  = b[threadIdx.x];
        sas[threadIdx.x] = a[threadIdx.x];
        sad[threadIdx.x] = a[OUT_DIM + threadIdx.x];
    }
    __syncthreads();

    int n = blockIdx.x * blockDim.x + threadIdx.x;
    if (n >= nN) return;

    const float4* __restrict__ x4 = (const float4*)(x + (size_t)n * IN_DIM);
    const float4* __restrict__ W4 = (const float4*)sW;

    float acc[OUT_DIM];
#pragma unroll
    for (int d = 0; d < OUT_DIM; d++) acc[d] = 0.f;

    for (int kk = 0; kk < IN_DIM / 4; kk++) {
        float4 xv = x4[kk];
#pragma unroll
        for (int d = 0; d < OUT_DIM; d++) {
            float4 wv = W4[d * (IN_DIM / 4) + kk];   // warp-broadcast from smem
            acc[d] += xv.x * wv.x + xv.y * wv.y + xv.z * wv.z + xv.w * wv.w;
        }
    }

    float ss = 0.f, sd = 0.f;
    uint2* newh = (uint2*)(g_newh + ((size_t)n << 6));
#pragma unroll
    for (int j = 0; j < OUT_DIM / 4; j++) {
        float v0 = acc[4*j+0] + sb[4*j+0];
        float v1 = acc[4*j+1] + sb[4*j+1];
        float v2 = acc[4*j+2] + sb[4*j+2];
        float v3 = acc[4*j+3] + sb[4*j+3];
        __half2 h0 = __float22half2_rn(make_float2(v0, v1));
        __half2 h1 = __float22half2_rn(make_float2(v2, v3));
        uint2 hv;
        hv.x = *(unsigned int*)&h0;
        hv.y = *(unsigned int*)&h1;
        newh[j] = hv;
        ss += v0*sas[4*j+0] + v1*sas[4*j+1] + v2*sas[4*j+2] + v3*sas[4*j+3];
        sd += v0*sad[4*j+0] + v1*sad[4*j+1] + v2*sad[4*j+2] + v3*sad[4*j+3];
    }
    g_ssrc[n] = ss;
    g_sdst[n] = sd;
}

// ---------------------------------------------------------------------------
// Kernel 2: exclusive scan of g_cnt -> g_base, decoupled lookback.
// ---------------------------------------------------------------------------
__global__ __launch_bounds__(SCAN_BLK) void k_scan(int nN)
{
    __shared__ int swarp[32];
    __shared__ int s_total;
    __shared__ int s_boff;
    int tid  = threadIdx.x;
    int lane = tid & 31;
    int wid  = tid >> 5;
    int bid  = blockIdx.x;
    int i    = bid * SCAN_BLK + tid;

    int v = (i < nN) ? g_cnt[i] : 0;

    int inc = v;
#pragma unroll
    for (int off = 1; off < 32; off <<= 1) {
        int t = __shfl_up_sync(0xFFFFFFFF, inc, off);
        if (lane >= off) inc += t;
    }
    if (lane == 31) swarp[wid] = inc;
    __syncthreads();
    if (wid == 0) {
        int wv = swarp[lane];
        int winc = wv;
#pragma unroll
        for (int off = 1; off < 32; off <<= 1) {
            int t = __shfl_up_sync(0xFFFFFFFF, winc, off);
            if (lane >= off) winc += t;
        }
        swarp[lane] = winc - wv;
    }
    __syncthreads();
    int incl = swarp[wid] + inc;
    if (tid == SCAN_BLK - 1) s_total = incl;
    __syncthreads();

    if (tid == 0) {
        g_bsum[bid] = s_total;
        __threadfence();
        *(volatile int*)&g_flag[bid] = 1;
    }

    if (wid == 0) {
        int off = 0;
        for (int base = 0; base < bid; base += 32) {
            int j = base + lane;
            int vj = 0;
            if (j < bid) {
                while (*(volatile int*)&g_flag[j] == 0) {}
                __threadfence();
                vj = *(volatile int*)&g_bsum[j];
            }
#pragma unroll
            for (int o = 16; o > 0; o >>= 1)
                vj += __shfl_down_sync(0xFFFFFFFF, vj, o);
            off += __shfl_sync(0xFFFFFFFF, vj, 0);
        }
        if (lane == 0) s_boff = off;
    }
    __syncthreads();

    if (i < nN) g_base[i] = s_boff + incl - v;
}

// ---------------------------------------------------------------------------
// Kernel 3: place, 2 edges/thread (int2 loads, 4 independent gathers in
// flight). Cursor atomic leaves g_base[n] == end[n].
// ---------------------------------------------------------------------------
__global__ __launch_bounds__(256) void k_place(
    const int* __restrict__ eidx, int nE, int nN)
{
    int i = blockIdx.x * blockDim.x + threadIdx.x;   // pair index
    int e0 = i * 2;
    if (e0 >= nE) return;

    if (e0 + 1 < nE) {
        int2 sp = ((const int2*)eidx)[i];
        int2 dp = ((const int2*)(eidx + nE))[i];
        int s0 = min(max(sp.x, 0), nN - 1), s1 = min(max(sp.y, 0), nN - 1);
        int d0 = min(max(dp.x, 0), nN - 1), d1 = min(max(dp.y, 0), nN - 1);
        float a0 = g_ssrc[s0], a1 = g_ssrc[s1];
        float b0 = g_sdst[d0], b1 = g_sdst[d1];
        float sc0 = a0 + b0, sc1 = a1 + b1;
        sc0 = sc0 > 0.f ? sc0 : SLOPE * sc0;
        sc1 = sc1 > 0.f ? sc1 : SLOPE * sc1;
        float ev0 = __expf(sc0), ev1 = __expf(sc1);
        int p0 = atomicAdd(&g_base[s0], 1);
        int p1 = atomicAdd(&g_base[s1], 1);
        g_edge[p0] = make_float2(ev0, __int_as_float(d0));
        g_edge[p1] = make_float2(ev1, __int_as_float(d1));
    } else {
        int s = min(max(eidx[e0], 0), nN - 1);
        int d = min(max(eidx[(size_t)nE + e0], 0), nN - 1);
        float sc = g_ssrc[s] + g_sdst[d];
        sc = sc > 0.f ? sc : SLOPE * sc;
        float ev = __expf(sc);
        int pos = atomicAdd(&g_base[s], 1);
        g_edge[pos] = make_float2(ev, __int_as_float(d));
    }
}

// ---------------------------------------------------------------------------
// Kernel 4: gather-aggregate + normalize. 8 lanes/node, lane c owns 16B of
// the fp16 row. Unrolled x4 for MLP. minBlocks=8 caps regs at 32 so 8 blocks
// (2048 thr) can be resident per SM — occupancy was 57% at 40 regs.
// ---------------------------------------------------------------------------
__global__ __launch_bounds__(256, 8) void k_aggregate(
    float* __restrict__ out, int nN)
{
    int n = blockIdx.x * 32 + (threadIdx.x >> 3);
    int c = threadIdx.x & 7;
    if (n >= nN) return;

    int beg = (n == 0) ? 0 : g_base[n - 1];
    int end = g_base[n];

    float acc[8];
#pragma unroll
    for (int j = 0; j < 8; j++) acc[j] = 0.f;
    float rs = 0.f;

    int i = beg;
    for (; i + 4 <= end; i += 4) {
        float2 p0 = g_edge[i];
        float2 p1 = g_edge[i + 1];
        float2 p2 = g_edge[i + 2];
        float2 p3 = g_edge[i + 3];
        uint4 h0 = *(const uint4*)(g_newh + ((size_t)__float_as_int(p0.y) << 6) + c * 8);
        uint4 h1 = *(const uint4*)(g_newh + ((size_t)__float_as_int(p1.y) << 6) + c * 8);
        uint4 h2 = *(const uint4*)(g_newh + ((size_t)__float_as_int(p2.y) << 6) + c * 8);
        uint4 h3 = *(const uint4*)(g_newh + ((size_t)__float_as_int(p3.y) << 6) + c * 8);
#pragma unroll
        for (int q = 0; q < 4; q++) {
            float ev = (q == 0) ? p0.x : (q == 1) ? p1.x : (q == 2) ? p2.x : p3.x;
            uint4 hv = (q == 0) ? h0 : (q == 1) ? h1 : (q == 2) ? h2 : h3;
            float2 f0 = __half22float2(*(__half2*)&hv.x);
            float2 f1 = __half22float2(*(__half2*)&hv.y);
            float2 f2 = __half22float2(*(__half2*)&hv.z);
            float2 f3 = __half22float2(*(__half2*)&hv.w);
            acc[0] += ev * f0.x;  acc[1] += ev * f0.y;
            acc[2] += ev * f1.x;  acc[3] += ev * f1.y;
            acc[4] += ev * f2.x;  acc[5] += ev * f2.y;
            acc[6] += ev * f3.x;  acc[7] += ev * f3.y;
            rs += ev;
        }
    }
    for (; i < end; i++) {
        float2 p = g_edge[i];
        uint4 hv = *(const uint4*)(g_newh + ((size_t)__float_as_int(p.y) << 6) + c * 8);
        float ev = p.x;
        float2 f0 = __half22float2(*(__half2*)&hv.x);
        float2 f1 = __half22float2(*(__half2*)&hv.y);
        float2 f2 = __half22float2(*(__half2*)&hv.z);
        float2 f3 = __half22float2(*(__half2*)&hv.w);
        acc[0] += ev * f0.x;  acc[1] += ev * f0.y;
        acc[2] += ev * f1.x;  acc[3] += ev * f1.y;
        acc[4] += ev * f2.x;  acc[5] += ev * f2.y;
        acc[6] += ev * f3.x;  acc[7] += ev * f3.y;
        rs += ev;
    }

    float inv = 1.f / (rs + EPS);
    float* op = out + ((size_t)n << 6) + c * 8;
    *(float4*)op       = make_float4(acc[0]*inv, acc[1]*inv, acc[2]*inv, acc[3]*inv);
    *(float4*)(op + 4) = make_float4(acc[4]*inv, acc[5]*inv, acc[6]*inv, acc[7]*inv);

    if (c == 0) g_cnt[n] = 0;   // clean for next launch (graph replay)
}

// ---------------------------------------------------------------------------
extern "C" void kernel_launch(void* const* d_in, const int* in_sizes, int n_in,
                              void* d_out, int out_size)
{
    const float* x    = (const float*)d_in[0];
    const int*   eidx = (const int*)d_in[1];    // int32 (JAX x64 disabled)
    const float* W    = (const float*)d_in[2];
    const float* b    = (const float*)d_in[3];
    const float* a    = (const float*)d_in[4];
    float* out = (float*)d_out;

    int nN = in_sizes[0] / IN_DIM;   // 50000
    int nE = in_sizes[1] / 2;        // 1600000

    int nbT = (nN + 255) / 256;
    int nbH = 1024;
    k_fused<<<nbT + nbH, 256>>>(x, W, b, a, eidx, nN, nE, nbT);

    int nbS = (nN + SCAN_BLK - 1) / SCAN_BLK;     // 49
    k_scan<<<nbS, SCAN_BLK>>>(nN);

    int pairs = (nE + 1) / 2;
    k_place<<<(pairs + 255) / 256, 256>>>(eidx, nE, nN);

    k_aggregate<<<(nN + 31) / 32, 256>>>(out, nN);
}

// round 10
// speedup vs baseline: 1.0408x; 1.0228x over previous
#include <cuda_runtime.h>
#include <cuda_fp16.h>
#include <cstdint>

#define IN_DIM 128
#define OUT_DIM 64
#define MAXN 50000
#define MAXE 1600000
#define SLOPE 0.1f
#define EPS 1e-12f
#define SCAN_BLK 1024
#define MAX_SCAN_BLOCKS 64

// Scratch (static device globals — allocation is forbidden). Zero-init at load.
__device__ __align__(256) __half g_newh[MAXN * OUT_DIM]; // transformed features, fp16
__device__ float  g_ssrc[MAXN];          // new[n] . a_src
__device__ float  g_sdst[MAXN];          // new[n] . a_dst
__device__ int    g_cnt[MAXN];           // out-degree histogram (zeroed by k_aggregate)
__device__ int    g_base[MAXN];          // CSR offsets (mutated by k_place into end[])
__device__ int    g_csr[MAXE];           // src-sorted dst indices (4B payload)
__device__ int    g_bsum[MAX_SCAN_BLOCKS];
__device__ int    g_flag[MAX_SCAN_BLOCKS];

// ---------------------------------------------------------------------------
// Kernel 1 (fused): blocks [0, nbT): transform new = x@W^T+b -> fp16, scores
//   (scalar FFMA, W broadcast from smem — proven R4 form).
//   Blocks [nbT, ...): histogram of src. Block 0 zeroes scan flags.
// ---------------------------------------------------------------------------
__global__ __launch_bounds__(256) void k_fused(
    const float* __restrict__ x, const float* __restrict__ W,
    const float* __restrict__ b, const float* __restrict__ a,
    const int* __restrict__ eidx, int nN, int nE, int nbT)
{
    if ((int)blockIdx.x >= nbT) {
        // ---- histogram part ----
        int tidg   = (blockIdx.x - nbT) * blockDim.x + threadIdx.x;
        int stride = (gridDim.x - nbT) * blockDim.x;
        for (int e = tidg; e < nE; e += stride) {
            int s = eidx[e];
            s = min(max(s, 0), nN - 1);
            atomicAdd(&g_cnt[s], 1);
        }
        return;
    }

    // ---- transform part ----
    if (blockIdx.x == 0 && threadIdx.x < MAX_SCAN_BLOCKS) g_flag[threadIdx.x] = 0;

    __shared__ __align__(16) float sW[OUT_DIM * IN_DIM];
    __shared__ float sb[OUT_DIM], sas[OUT_DIM], sad[OUT_DIM];
    for (int i = threadIdx.x; i < OUT_DIM * IN_DIM; i += blockDim.x) sW[i] = W[i];
    if (threadIdx.x < OUT_DIM) {
        sb[threadIdx.x]  = b[threadIdx.x];
        sas[threadIdx.x] = a[threadIdx.x];
        sad[threadIdx.x] = a[OUT_DIM + threadIdx.x];
    }
    __syncthreads();

    int n = blockIdx.x * blockDim.x + threadIdx.x;
    if (n >= nN) return;

    const float4* __restrict__ x4 = (const float4*)(x + (size_t)n * IN_DIM);
    const float4* __restrict__ W4 = (const float4*)sW;

    float acc[OUT_DIM];
#pragma unroll
    for (int d = 0; d < OUT_DIM; d++) acc[d] = 0.f;

    for (int kk = 0; kk < IN_DIM / 4; kk++) {
        float4 xv = x4[kk];
#pragma unroll
        for (int d = 0; d < OUT_DIM; d++) {
            float4 wv = W4[d * (IN_DIM / 4) + kk];   // warp-broadcast from smem
            acc[d] += xv.x * wv.x + xv.y * wv.y + xv.z * wv.z + xv.w * wv.w;
        }
    }

    float ss = 0.f, sd = 0.f;
    uint2* newh = (uint2*)(g_newh + ((size_t)n << 6));
#pragma unroll
    for (int j = 0; j < OUT_DIM / 4; j++) {
        float v0 = acc[4*j+0] + sb[4*j+0];
        float v1 = acc[4*j+1] + sb[4*j+1];
        float v2 = acc[4*j+2] + sb[4*j+2];
        float v3 = acc[4*j+3] + sb[4*j+3];
        __half2 h0 = __float22half2_rn(make_float2(v0, v1));
        __half2 h1 = __float22half2_rn(make_float2(v2, v3));
        uint2 hv;
        hv.x = *(unsigned int*)&h0;
        hv.y = *(unsigned int*)&h1;
        newh[j] = hv;
        ss += v0*sas[4*j+0] + v1*sas[4*j+1] + v2*sas[4*j+2] + v3*sas[4*j+3];
        sd += v0*sad[4*j+0] + v1*sad[4*j+1] + v2*sad[4*j+2] + v3*sad[4*j+3];
    }
    g_ssrc[n] = ss;
    g_sdst[n] = sd;
}

// ---------------------------------------------------------------------------
// Kernel 2: exclusive scan of g_cnt -> g_base, decoupled lookback.
// ---------------------------------------------------------------------------
__global__ __launch_bounds__(SCAN_BLK) void k_scan(int nN)
{
    __shared__ int swarp[32];
    __shared__ int s_total;
    __shared__ int s_boff;
    int tid  = threadIdx.x;
    int lane = tid & 31;
    int wid  = tid >> 5;
    int bid  = blockIdx.x;
    int i    = bid * SCAN_BLK + tid;

    int v = (i < nN) ? g_cnt[i] : 0;

    int inc = v;
#pragma unroll
    for (int off = 1; off < 32; off <<= 1) {
        int t = __shfl_up_sync(0xFFFFFFFF, inc, off);
        if (lane >= off) inc += t;
    }
    if (lane == 31) swarp[wid] = inc;
    __syncthreads();
    if (wid == 0) {
        int wv = swarp[lane];
        int winc = wv;
#pragma unroll
        for (int off = 1; off < 32; off <<= 1) {
            int t = __shfl_up_sync(0xFFFFFFFF, winc, off);
            if (lane >= off) winc += t;
        }
        swarp[lane] = winc - wv;
    }
    __syncthreads();
    int incl = swarp[wid] + inc;
    if (tid == SCAN_BLK - 1) s_total = incl;
    __syncthreads();

    if (tid == 0) {
        g_bsum[bid] = s_total;
        __threadfence();
        *(volatile int*)&g_flag[bid] = 1;
    }

    if (wid == 0) {
        int off = 0;
        for (int base = 0; base < bid; base += 32) {
            int j = base + lane;
            int vj = 0;
            if (j < bid) {
                while (*(volatile int*)&g_flag[j] == 0) {}
                __threadfence();
                vj = *(volatile int*)&g_bsum[j];
            }
#pragma unroll
            for (int o = 16; o > 0; o >>= 1)
                vj += __shfl_down_sync(0xFFFFFFFF, vj, o);
            off += __shfl_sync(0xFFFFFFFF, vj, 0);
        }
        if (lane == 0) s_boff = off;
    }
    __syncthreads();

    if (i < nN) g_base[i] = s_boff + incl - v;
}

// ---------------------------------------------------------------------------
// Kernel 3: place dst (4B) into CSR slot — no gathers, no exp here.
// Cursor atomic leaves g_base[n] == end[n].
// ---------------------------------------------------------------------------
__global__ __launch_bounds__(256) void k_place(
    const int* __restrict__ eidx, int nE, int nN)
{
    int e = blockIdx.x * blockDim.x + threadIdx.x;
    if (e >= nE) return;
    int s = eidx[e];
    int d = eidx[(size_t)nE + e];
    s = min(max(s, 0), nN - 1);
    d = min(max(d, 0), nN - 1);
    int pos = atomicAdd(&g_base[s], 1);
    g_csr[pos] = d;
}

// ---------------------------------------------------------------------------
// Kernel 4: gather-aggregate + normalize. 8 lanes/node, lane c owns 16B of
// the fp16 row. Score/exp recomputed here: issued once per warp instruction,
// so the 8-lane redundancy is free; sdst[dst] is a same-address (broadcast)
// load within each group. Unrolled x4 for MLP. Re-zeroes g_cnt for replay.
// ---------------------------------------------------------------------------
__global__ __launch_bounds__(256) void k_aggregate(
    float* __restrict__ out, int nN)
{
    int n = blockIdx.x * 32 + (threadIdx.x >> 3);
    int c = threadIdx.x & 7;
    if (n >= nN) return;

    int beg = (n == 0) ? 0 : g_base[n - 1];
    int end = g_base[n];
    float ssn = g_ssrc[n];

    float acc[8];
#pragma unroll
    for (int j = 0; j < 8; j++) acc[j] = 0.f;
    float rs = 0.f;

    int i = beg;
    for (; i + 4 <= end; i += 4) {
        int dst0 = g_csr[i];
        int dst1 = g_csr[i + 1];
        int dst2 = g_csr[i + 2];
        int dst3 = g_csr[i + 3];
        float sd0 = g_sdst[dst0];
        float sd1 = g_sdst[dst1];
        float sd2 = g_sdst[dst2];
        float sd3 = g_sdst[dst3];
        uint4 h0 = *(const uint4*)(g_newh + ((size_t)dst0 << 6) + c * 8);
        uint4 h1 = *(const uint4*)(g_newh + ((size_t)dst1 << 6) + c * 8);
        uint4 h2 = *(const uint4*)(g_newh + ((size_t)dst2 << 6) + c * 8);
        uint4 h3 = *(const uint4*)(g_newh + ((size_t)dst3 << 6) + c * 8);
        float sc0 = ssn + sd0;  sc0 = sc0 > 0.f ? sc0 : SLOPE * sc0;
        float sc1 = ssn + sd1;  sc1 = sc1 > 0.f ? sc1 : SLOPE * sc1;
        float sc2 = ssn + sd2;  sc2 = sc2 > 0.f ? sc2 : SLOPE * sc2;
        float sc3 = ssn + sd3;  sc3 = sc3 > 0.f ? sc3 : SLOPE * sc3;
        float ev0 = __expf(sc0);
        float ev1 = __expf(sc1);
        float ev2 = __expf(sc2);
        float ev3 = __expf(sc3);
#pragma unroll
        for (int q = 0; q < 4; q++) {
            float ev = (q == 0) ? ev0 : (q == 1) ? ev1 : (q == 2) ? ev2 : ev3;
            uint4 hv = (q == 0) ? h0 : (q == 1) ? h1 : (q == 2) ? h2 : h3;
            float2 f0 = __half22float2(*(__half2*)&hv.x);
            float2 f1 = __half22float2(*(__half2*)&hv.y);
            float2 f2 = __half22float2(*(__half2*)&hv.z);
            float2 f3 = __half22float2(*(__half2*)&hv.w);
            acc[0] += ev * f0.x;  acc[1] += ev * f0.y;
            acc[2] += ev * f1.x;  acc[3] += ev * f1.y;
            acc[4] += ev * f2.x;  acc[5] += ev * f2.y;
            acc[6] += ev * f3.x;  acc[7] += ev * f3.y;
            rs += ev;
        }
    }
    for (; i < end; i++) {
        int dst = g_csr[i];
        float sc = ssn + g_sdst[dst];
        sc = sc > 0.f ? sc : SLOPE * sc;
        float ev = __expf(sc);
        uint4 hv = *(const uint4*)(g_newh + ((size_t)dst << 6) + c * 8);
        float2 f0 = __half22float2(*(__half2*)&hv.x);
        float2 f1 = __half22float2(*(__half2*)&hv.y);
        float2 f2 = __half22float2(*(__half2*)&hv.z);
        float2 f3 = __half22float2(*(__half2*)&hv.w);
        acc[0] += ev * f0.x;  acc[1] += ev * f0.y;
        acc[2] += ev * f1.x;  acc[3] += ev * f1.y;
        acc[4] += ev * f2.x;  acc[5] += ev * f2.y;
        acc[6] += ev * f3.x;  acc[7] += ev * f3.y;
        rs += ev;
    }

    float inv = 1.f / (rs + EPS);
    float* op = out + ((size_t)n << 6) + c * 8;
    *(float4*)op       = make_float4(acc[0]*inv, acc[1]*inv, acc[2]*inv, acc[3]*inv);
    *(float4*)(op + 4) = make_float4(acc[4]*inv, acc[5]*inv, acc[6]*inv, acc[7]*inv);

    if (c == 0) g_cnt[n] = 0;   // clean for next launch (graph replay)
}

// ---------------------------------------------------------------------------
extern "C" void kernel_launch(void* const* d_in, const int* in_sizes, int n_in,
                              void* d_out, int out_size)
{
    const float* x    = (const float*)d_in[0];
    const int*   eidx = (const int*)d_in[1];    // int32 (JAX x64 disabled)
    const float* W    = (const float*)d_in[2];
    const float* b    = (const float*)d_in[3];
    const float* a    = (const float*)d_in[4];
    float* out = (float*)d_out;

    int nN = in_sizes[0] / IN_DIM;   // 50000
    int nE = in_sizes[1] / 2;        // 1600000

    int nbT = (nN + 255) / 256;
    int nbH = 1024;
    k_fused<<<nbT + nbH, 256>>>(x, W, b, a, eidx, nN, nE, nbT);

    int nbS = (nN + SCAN_BLK - 1) / SCAN_BLK;     // 49
    k_scan<<<nbS, SCAN_BLK>>>(nN);

    k_place<<<(nE + 255) / 256, 256>>>(eidx, nE, nN);

    k_aggregate<<<(nN + 31) / 32, 256>>>(out, nN);
}

// round 11
// speedup vs baseline: 1.0487x; 1.0076x over previous
#include <cuda_runtime.h>
#include <cuda_fp16.h>
#include <cstdint>

#define IN_DIM 128
#define OUT_DIM 64
#define MAXN 50000
#define MAXE 1600000
#define SLOPE 0.1f
#define EPS 1e-12f
#define SCAN_BLK 1024
#define MAX_SCAN_BLOCKS 64

// Scratch (static device globals — allocation is forbidden). Zero-init at load.
__device__ __align__(256) __half g_newh[MAXN * OUT_DIM]; // transformed features, fp16
__device__ float  g_ssrc[MAXN];          // new[n] . a_src
__device__ float  g_sdst[MAXN];          // new[n] . a_dst
__device__ int    g_cnt[MAXN];           // out-degree histogram (zeroed by k_aggregate)
__device__ int    g_base[MAXN];          // CSR offsets (mutated by k_place into end[])
__device__ int    g_csr[MAXE];           // src-sorted dst indices (4B payload)
__device__ int    g_bsum[MAX_SCAN_BLOCKS];
__device__ int    g_flag[MAX_SCAN_BLOCKS];

// ---------------------------------------------------------------------------
// Kernel 1 (fused): blocks [0, nbT): transform new = x@W^T+b -> fp16, scores
//   (scalar FFMA, W broadcast from smem — proven R4 form).
//   Blocks [nbT, ...): histogram of src. Block 0 zeroes scan flags.
// ---------------------------------------------------------------------------
__global__ __launch_bounds__(256) void k_fused(
    const float* __restrict__ x, const float* __restrict__ W,
    const float* __restrict__ b, const float* __restrict__ a,
    const int* __restrict__ eidx, int nN, int nE, int nbT)
{
    if ((int)blockIdx.x >= nbT) {
        // ---- histogram part ----
        int tidg   = (blockIdx.x - nbT) * blockDim.x + threadIdx.x;
        int stride = (gridDim.x - nbT) * blockDim.x;
        for (int e = tidg; e < nE; e += stride) {
            int s = eidx[e];
            s = min(max(s, 0), nN - 1);
            atomicAdd(&g_cnt[s], 1);
        }
        return;
    }

    // ---- transform part ----
    if (blockIdx.x == 0 && threadIdx.x < MAX_SCAN_BLOCKS) g_flag[threadIdx.x] = 0;

    __shared__ __align__(16) float sW[OUT_DIM * IN_DIM];
    __shared__ float sb[OUT_DIM], sas[OUT_DIM], sad[OUT_DIM];
    for (int i = threadIdx.x; i < OUT_DIM * IN_DIM; i += blockDim.x) sW[i] = W[i];
    if (threadIdx.x < OUT_DIM) {
        sb[threadIdx.x]  = b[threadIdx.x];
        sas[threadIdx.x] = a[threadIdx.x];
        sad[threadIdx.x] = a[OUT_DIM + threadIdx.x];
    }
    __syncthreads();

    int n = blockIdx.x * blockDim.x + threadIdx.x;
    if (n >= nN) return;

    const float4* __restrict__ x4 = (const float4*)(x + (size_t)n * IN_DIM);
    const float4* __restrict__ W4 = (const float4*)sW;

    float acc[OUT_DIM];
#pragma unroll
    for (int d = 0; d < OUT_DIM; d++) acc[d] = 0.f;

    for (int kk = 0; kk < IN_DIM / 4; kk++) {
        float4 xv = x4[kk];
#pragma unroll
        for (int d = 0; d < OUT_DIM; d++) {
            float4 wv = W4[d * (IN_DIM / 4) + kk];   // warp-broadcast from smem
            acc[d] += xv.x * wv.x + xv.y * wv.y + xv.z * wv.z + xv.w * wv.w;
        }
    }

    float ss = 0.f, sd = 0.f;
    uint2* newh = (uint2*)(g_newh + ((size_t)n << 6));
#pragma unroll
    for (int j = 0; j < OUT_DIM / 4; j++) {
        float v0 = acc[4*j+0] + sb[4*j+0];
        float v1 = acc[4*j+1] + sb[4*j+1];
        float v2 = acc[4*j+2] + sb[4*j+2];
        float v3 = acc[4*j+3] + sb[4*j+3];
        __half2 h0 = __float22half2_rn(make_float2(v0, v1));
        __half2 h1 = __float22half2_rn(make_float2(v2, v3));
        uint2 hv;
        hv.x = *(unsigned int*)&h0;
        hv.y = *(unsigned int*)&h1;
        newh[j] = hv;
        ss += v0*sas[4*j+0] + v1*sas[4*j+1] + v2*sas[4*j+2] + v3*sas[4*j+3];
        sd += v0*sad[4*j+0] + v1*sad[4*j+1] + v2*sad[4*j+2] + v3*sad[4*j+3];
    }
    g_ssrc[n] = ss;
    g_sdst[n] = sd;
}

// ---------------------------------------------------------------------------
// Kernel 2: exclusive scan of g_cnt -> g_base, decoupled lookback.
// ---------------------------------------------------------------------------
__global__ __launch_bounds__(SCAN_BLK) void k_scan(int nN)
{
    __shared__ int swarp[32];
    __shared__ int s_total;
    __shared__ int s_boff;
    int tid  = threadIdx.x;
    int lane = tid & 31;
    int wid  = tid >> 5;
    int bid  = blockIdx.x;
    int i    = bid * SCAN_BLK + tid;

    int v = (i < nN) ? g_cnt[i] : 0;

    int inc = v;
#pragma unroll
    for (int off = 1; off < 32; off <<= 1) {
        int t = __shfl_up_sync(0xFFFFFFFF, inc, off);
        if (lane >= off) inc += t;
    }
    if (lane == 31) swarp[wid] = inc;
    __syncthreads();
    if (wid == 0) {
        int wv = swarp[lane];
        int winc = wv;
#pragma unroll
        for (int off = 1; off < 32; off <<= 1) {
            int t = __shfl_up_sync(0xFFFFFFFF, winc, off);
            if (lane >= off) winc += t;
        }
        swarp[lane] = winc - wv;
    }
    __syncthreads();
    int incl = swarp[wid] + inc;
    if (tid == SCAN_BLK - 1) s_total = incl;
    __syncthreads();

    if (tid == 0) {
        g_bsum[bid] = s_total;
        __threadfence();
        *(volatile int*)&g_flag[bid] = 1;
    }

    if (wid == 0) {
        int off = 0;
        for (int base = 0; base < bid; base += 32) {
            int j = base + lane;
            int vj = 0;
            if (j < bid) {
                while (*(volatile int*)&g_flag[j] == 0) {}
                __threadfence();
                vj = *(volatile int*)&g_bsum[j];
            }
#pragma unroll
            for (int o = 16; o > 0; o >>= 1)
                vj += __shfl_down_sync(0xFFFFFFFF, vj, o);
            off += __shfl_sync(0xFFFFFFFF, vj, 0);
        }
        if (lane == 0) s_boff = off;
    }
    __syncthreads();

    if (i < nN) g_base[i] = s_boff + incl - v;
}

// ---------------------------------------------------------------------------
// Kernel 3: place dst (4B) into CSR slot — no gathers, no exp here.
// Cursor atomic leaves g_base[n] == end[n].
// ---------------------------------------------------------------------------
__global__ __launch_bounds__(256) void k_place(
    const int* __restrict__ eidx, int nE, int nN)
{
    int e = blockIdx.x * blockDim.x + threadIdx.x;
    if (e >= nE) return;
    int s = eidx[e];
    int d = eidx[(size_t)nE + e];
    s = min(max(s, 0), nN - 1);
    d = min(max(d, 0), nN - 1);
    int pos = atomicAdd(&g_base[s], 1);
    g_csr[pos] = d;
}

// ---------------------------------------------------------------------------
// Kernel 4: gather-aggregate + normalize. 8 lanes/node, lane c owns 16B of
// the fp16 row. Score/exp recomputed here: issued once per warp instruction,
// so the 8-lane redundancy is free; sdst[dst] is a same-address (broadcast)
// load within each group. Unrolled x4 for MLP. Re-zeroes g_cnt for replay.
// ---------------------------------------------------------------------------
__global__ __launch_bounds__(256) void k_aggregate(
    float* __restrict__ out, int nN)
{
    int n = blockIdx.x * 32 + (threadIdx.x >> 3);
    int c = threadIdx.x & 7;
    if (n >= nN) return;

    int beg = (n == 0) ? 0 : g_base[n - 1];
    int end = g_base[n];
    float ssn = g_ssrc[n];

    float acc[8];
#pragma unroll
    for (int j = 0; j < 8; j++) acc[j] = 0.f;
    float rs = 0.f;

    int i = beg;
    for (; i + 4 <= end; i += 4) {
        int dst0 = g_csr[i];
        int dst1 = g_csr[i + 1];
        int dst2 = g_csr[i + 2];
        int dst3 = g_csr[i + 3];
        float sd0 = g_sdst[dst0];
        float sd1 = g_sdst[dst1];
        float sd2 = g_sdst[dst2];
        float sd3 = g_sdst[dst3];
        uint4 h0 = *(const uint4*)(g_newh + ((size_t)dst0 << 6) + c * 8);
        uint4 h1 = *(const uint4*)(g_newh + ((size_t)dst1 << 6) + c * 8);
        uint4 h2 = *(const uint4*)(g_newh + ((size_t)dst2 << 6) + c * 8);
        uint4 h3 = *(const uint4*)(g_newh + ((size_t)dst3 << 6) + c * 8);
        float sc0 = ssn + sd0;  sc0 = sc0 > 0.f ? sc0 : SLOPE * sc0;
        float sc1 = ssn + sd1;  sc1 = sc1 > 0.f ? sc1 : SLOPE * sc1;
        float sc2 = ssn + sd2;  sc2 = sc2 > 0.f ? sc2 : SLOPE * sc2;
        float sc3 = ssn + sd3;  sc3 = sc3 > 0.f ? sc3 : SLOPE * sc3;
        float ev0 = __expf(sc0);
        float ev1 = __expf(sc1);
        float ev2 = __expf(sc2);
        float ev3 = __expf(sc3);
#pragma unroll
        for (int q = 0; q < 4; q++) {
            float ev = (q == 0) ? ev0 : (q == 1) ? ev1 : (q == 2) ? ev2 : ev3;
            uint4 hv = (q == 0) ? h0 : (q == 1) ? h1 : (q == 2) ? h2 : h3;
            float2 f0 = __half22float2(*(__half2*)&hv.x);
            float2 f1 = __half22float2(*(__half2*)&hv.y);
            float2 f2 = __half22float2(*(__half2*)&hv.z);
            float2 f3 = __half22float2(*(__half2*)&hv.w);
            acc[0] += ev * f0.x;  acc[1] += ev * f0.y;
            acc[2] += ev * f1.x;  acc[3] += ev * f1.y;
            acc[4] += ev * f2.x;  acc[5] += ev * f2.y;
            acc[6] += ev * f3.x;  acc[7] += ev * f3.y;
            rs += ev;
        }
    }
    for (; i < end; i++) {
        int dst = g_csr[i];
        float sc = ssn + g_sdst[dst];
        sc = sc > 0.f ? sc : SLOPE * sc;
        float ev = __expf(sc);
        uint4 hv = *(const uint4*)(g_newh + ((size_t)dst << 6) + c * 8);
        float2 f0 = __half22float2(*(__half2*)&hv.x);
        float2 f1 = __half22float2(*(__half2*)&hv.y);
        float2 f2 = __half22float2(*(__half2*)&hv.z);
        float2 f3 = __half22float2(*(__half2*)&hv.w);
        acc[0] += ev * f0.x;  acc[1] += ev * f0.y;
        acc[2] += ev * f1.x;  acc[3] += ev * f1.y;
        acc[4] += ev * f2.x;  acc[5] += ev * f2.y;
        acc[6] += ev * f3.x;  acc[7] += ev * f3.y;
        rs += ev;
    }

    float inv = 1.f / (rs + EPS);
    float* op = out + ((size_t)n << 6) + c * 8;
    *(float4*)op       = make_float4(acc[0]*inv, acc[1]*inv, acc[2]*inv, acc[3]*inv);
    *(float4*)(op + 4) = make_float4(acc[4]*inv, acc[5]*inv, acc[6]*inv, acc[7]*inv);

    if (c == 0) g_cnt[n] = 0;   // clean for next launch (graph replay)
}

// ---------------------------------------------------------------------------
extern "C" void kernel_launch(void* const* d_in, const int* in_sizes, int n_in,
                              void* d_out, int out_size)
{
    const float* x    = (const float*)d_in[0];
    const int*   eidx = (const int*)d_in[1];    // int32 (JAX x64 disabled)
    const float* W    = (const float*)d_in[2];
    const float* b    = (const float*)d_in[3];
    const float* a    = (const float*)d_in[4];
    float* out = (float*)d_out;

    int nN = in_sizes[0] / IN_DIM;   // 50000
    int nE = in_sizes[1] / 2;        // 1600000

    int nbT = (nN + 255) / 256;
    int nbH = 1024;
    k_fused<<<nbT + nbH, 256>>>(x, W, b, a, eidx, nN, nE, nbT);

    int nbS = (nN + SCAN_BLK - 1) / SCAN_BLK;     // 49
    k_scan<<<nbS, SCAN_BLK>>>(nN);

    k_place<<<(nE + 255) / 256, 256>>>(eidx, nE, nN);

    k_aggregate<<<(nN + 31) / 32, 256>>>(out, nN);
}